// round 1
// baseline (speedup 1.0000x reference)
#include <cuda_runtime.h>

// LayerNorm over last axis. Shapes: input/gamma/beta/out all [B*S, D] = [8192, 1024] fp32.
// One CTA per row, 256 threads, one float4 per thread held in registers.

#define THREADS 256
#define EPS 5e-06f

__global__ __launch_bounds__(THREADS) void layernorm_kernel(
    const float* __restrict__ input,
    const float* __restrict__ gamma,
    const float* __restrict__ beta,
    float* __restrict__ out,
    int D)  // D = 1024, D/4 = 256 = THREADS
{
    const long long row = blockIdx.x;
    const long long base = row * (long long)D;
    const int tid = threadIdx.x;

    // Each thread loads one float4 of the row.
    const float4* in4 = reinterpret_cast<const float4*>(input + base);
    float4 x = in4[tid];

    // Per-thread partial sums.
    float s  = x.x + x.y + x.z + x.w;
    float ss = x.x * x.x + x.y * x.y + x.z * x.z + x.w * x.w;

    // Warp reduction.
    #pragma unroll
    for (int off = 16; off > 0; off >>= 1) {
        s  += __shfl_xor_sync(0xFFFFFFFFu, s,  off);
        ss += __shfl_xor_sync(0xFFFFFFFFu, ss, off);
    }

    // Block reduction across 8 warps.
    __shared__ float sh_s[8];
    __shared__ float sh_ss[8];
    const int warp = tid >> 5;
    const int lane = tid & 31;
    if (lane == 0) { sh_s[warp] = s; sh_ss[warp] = ss; }
    __syncthreads();

    if (warp == 0) {
        float ws  = (lane < 8) ? sh_s[lane]  : 0.0f;
        float wss = (lane < 8) ? sh_ss[lane] : 0.0f;
        #pragma unroll
        for (int off = 4; off > 0; off >>= 1) {
            ws  += __shfl_xor_sync(0xFFFFFFFFu, ws,  off);
            wss += __shfl_xor_sync(0xFFFFFFFFu, wss, off);
        }
        if (lane == 0) {
            const float invD = 1.0f / (float)D;
            float mean = ws * invD;
            float var  = wss * invD - mean * mean;
            sh_s[0]  = mean;
            sh_ss[0] = rsqrtf(var + EPS);
        }
    }
    __syncthreads();

    const float mean = sh_s[0];
    const float rstd = sh_ss[0];

    // Load gamma/beta, fuse, store.
    const float4* g4 = reinterpret_cast<const float4*>(gamma + base);
    const float4* b4 = reinterpret_cast<const float4*>(beta + base);
    float4 g = g4[tid];
    float4 b = b4[tid];

    float4 o;
    o.x = (x.x - mean) * rstd * g.x + b.x;
    o.y = (x.y - mean) * rstd * g.y + b.y;
    o.z = (x.z - mean) * rstd * g.z + b.z;
    o.w = (x.w - mean) * rstd * g.w + b.w;

    float4* out4 = reinterpret_cast<float4*>(out + base);
    out4[tid] = o;
}

extern "C" void kernel_launch(void* const* d_in, const int* in_sizes, int n_in,
                              void* d_out, int out_size) {
    const float* input = (const float*)d_in[0];
    const float* gamma = (const float*)d_in[1];
    const float* beta  = (const float*)d_in[2];
    float* out = (float*)d_out;

    const int D = 1024;
    const int rows = out_size / D;  // 8192

    layernorm_kernel<<<rows, THREADS>>>(input, gamma, beta, out, D);
}